// round 16
// baseline (speedup 1.0000x reference)
#include <cuda_runtime.h>
#include <math.h>
#include <stdint.h>

#define HEADS 4
#define BB 8
#define NN 1024
#define CC 256
#define DD 64
#define QT 32            // query rows per CTA
#define KC 64            // keys per chunk
#define NCH 16           // chunks

#define KP 68            // K pitch: (4fr+fq)%32 distinct -> conflict-free B frags
#define VP 72            // V pitch: (8fq+fr)%32 distinct -> conflict-free B frags
#define DMP 68           // dis/mask pitch (mult of 4 for cp.async 16B alignment)
#define OP 68            // O scratch pitch (overlaid on Q staging)

// float-index smem offsets
#define Q_F   0                      // 32*68 = 2176 (reused as O scratch)
#define OS_F  0
#define K_F   2176                   // 2 * 64*68 = 8704
#define V_F   10880                  // 2 * 64*72 = 9216
#define D_F   20096                  // 2 * 32*68 = 4352
#define M_F   24448                  // 2 * 32*68 = 4352
#define RS_F  28800                  // 32
#define SMEM_FLOATS 28832
#define SMEM_BYTES (SMEM_FLOATS*4)   // 115328 -> 2 CTAs/SM (230656 <= 233472)

#define KSTR (KC*KP)
#define VSTR (KC*VP)
#define DSTR (QT*DMP)

#define CP_COMMIT   asm volatile("cp.async.commit_group;" ::: "memory")
#define CP_WAIT0    asm volatile("cp.async.wait_group 0;" ::: "memory")

static __device__ __forceinline__ uint32_t s2u(const void* p){
    uint32_t a;
    asm("{ .reg .u64 t; cvta.to.shared.u64 t, %1; cvt.u32.u64 %0, t; }" : "=r"(a) : "l"(p));
    return a;
}
static __device__ __forceinline__ uint32_t f2tf32(float f){
    uint32_t u; asm("cvt.rna.tf32.f32 %0, %1;" : "=r"(u) : "f"(f)); return u;
}
static __device__ __forceinline__ void mma_tf32(float* c, const uint32_t* a,
                                                uint32_t b0, uint32_t b1){
    asm volatile("mma.sync.aligned.m16n8k8.row.col.f32.tf32.tf32.f32 "
        "{%0,%1,%2,%3}, {%4,%5,%6,%7}, {%8,%9}, {%0,%1,%2,%3};"
        : "+f"(c[0]), "+f"(c[1]), "+f"(c[2]), "+f"(c[3])
        : "r"(a[0]), "r"(a[1]), "r"(a[2]), "r"(a[3]), "r"(b0), "r"(b1));
}
#define CPA16(dst, src) \
    asm volatile("cp.async.ca.shared.global [%0], [%1], 16;" :: "r"(dst), "l"(src) : "memory")

__global__ __launch_bounds__(256, 2)
void attn_fuse64_kernel(const float* __restrict__ q,
                        const float* __restrict__ k,
                        const float* __restrict__ v,
                        const unsigned int* __restrict__ mask,
                        const float* __restrict__ dis,
                        float* __restrict__ out,
                        float* __restrict__ pout)
{
    extern __shared__ float smf[];
    uint32_t* smu = (uint32_t*)smf;
    const uint32_t sbase = s2u(smf);

    const int tid  = threadIdx.x;
    const int wid  = tid >> 5;
    const int lane = tid & 31;
    const int fr = lane >> 2, fq = lane & 3;
    const int wr = wid >> 2, wc = wid & 3;     // 2 row-groups x 4 col-groups (16 keys each)
    const int h    = blockIdx.x & 3;           // heads fastest -> dis/mask L2 reuse
    const int tile = blockIdx.x >> 2;
    const int b    = blockIdx.y;
    const int row0 = tile * QT;

    const float* qbase = q + ((size_t)b * NN + row0) * CC + h * DD;
    const float* kbase = k + ((size_t)b * NN) * CC + h * DD;
    const float* vbase = v + ((size_t)b * NN) * CC + h * DD;
    const float* disbase = dis + ((size_t)b * NN + row0) * NN;
    const unsigned int* mbase = mask + ((size_t)b * NN + row0) * NN;
    float* pbase = pout + (((size_t)h * BB + b) * NN + row0) * NN;

    // staging coords
    const int kvr = tid >> 2, kvc = (tid & 3) * 16;   // K/V: 64 rows x 64 floats
    const int dmr = tid >> 3, dmc = (tid & 7) * 8;    // dis/mask: 32 rows x 64 elems

    // ---- issue chunk 0 (K,V,dis,mask) ----
    {
        const float* ks = kbase + (size_t)kvr * CC + kvc;
        const float* vs = vbase + (size_t)kvr * CC + kvc;
        uint32_t kd = sbase + (uint32_t)(K_F + kvr*KP + kvc)*4u;
        uint32_t vd = sbase + (uint32_t)(V_F + kvr*VP + kvc)*4u;
        #pragma unroll
        for (int i = 0; i < 4; i++){ CPA16(kd + 16u*i, ks + 4*i); CPA16(vd + 16u*i, vs + 4*i); }
        uint32_t dd = sbase + (uint32_t)(D_F + dmr*DMP + dmc)*4u;
        uint32_t md = sbase + (uint32_t)(M_F + dmr*DMP + dmc)*4u;
        CPA16(dd, disbase + (size_t)dmr*NN + dmc); CPA16(dd+16u, disbase + (size_t)dmr*NN + dmc + 4);
        CPA16(md, mbase   + (size_t)dmr*NN + dmc); CPA16(md+16u, mbase   + (size_t)dmr*NN + dmc + 4);
    }
    CP_COMMIT;

    // ---- stage Q (fp32 -> tf32) ----
    {
        const float* src = qbase + (size_t)dmr * CC + dmc;
        float4 v0 = *(const float4*)src;
        float4 v1 = *(const float4*)(src + 4);
        uint32_t* d = smu + Q_F + dmr * OP + dmc;
        *(uint4*)d       = make_uint4(f2tf32(v0.x), f2tf32(v0.y), f2tf32(v0.z), f2tf32(v0.w));
        *(uint4*)(d + 4) = make_uint4(f2tf32(v1.x), f2tf32(v1.y), f2tf32(v1.z), f2tf32(v1.w));
    }
    __syncthreads();

    // ---- hoist Q fragments, then free the region for O scratch ----
    uint32_t qf[8][4];
    #pragma unroll
    for (int kt = 0; kt < 8; kt++){
        const uint32_t* q0 = smu + Q_F + (wr*16 + fr) * OP + 8*kt + fq;
        qf[kt][0] = q0[0];
        qf[kt][1] = q0[8*OP];
        qf[kt][2] = q0[4];
        qf[kt][3] = q0[8*OP + 4];
    }
    __syncthreads();
    for (int i = tid; i < QT*OP; i += 256) smf[OS_F + i] = 0.0f;   // zero O scratch ONLY
    if (tid < 32) smf[RS_F + tid] = 0.0f;                          // zero rowsums

    const int r1 = wr*16 + fr;              // CTA-local row
    const int srcA = (lane & 28) | (fq >> 1);
    const int srcB = srcA + 2;
    const bool odd = (fq & 1);

    float psum0 = 0.f, psum1 = 0.f;
    float oacc[8][4];
    #pragma unroll
    for (int dt = 0; dt < 8; dt++)
        #pragma unroll
        for (int i = 0; i < 4; i++) oacc[dt][i] = 0.f;

    // ================= fused mainloop (16 iters) =================
    for (int c = 0; c < NCH; c++){
        CP_WAIT0;
        __syncthreads();               // publish chunk c; retire reads of chunk c-1

        if (c + 1 < NCH){              // prefetch chunk c+1
            int bb1 = (c + 1) & 1;
            const float* ks = kbase + (size_t)((c+1)*KC + kvr) * CC + kvc;
            const float* vs = vbase + (size_t)((c+1)*KC + kvr) * CC + kvc;
            uint32_t kd = sbase + (uint32_t)(K_F + bb1*KSTR + kvr*KP + kvc)*4u;
            uint32_t vd = sbase + (uint32_t)(V_F + bb1*VSTR + kvr*VP + kvc)*4u;
            #pragma unroll
            for (int i = 0; i < 4; i++){ CPA16(kd + 16u*i, ks + 4*i); CPA16(vd + 16u*i, vs + 4*i); }
            uint32_t dd = sbase + (uint32_t)(D_F + bb1*DSTR + dmr*DMP + dmc)*4u;
            uint32_t md = sbase + (uint32_t)(M_F + bb1*DSTR + dmr*DMP + dmc)*4u;
            const float* dsp = disbase + (size_t)dmr*NN + (c+1)*KC + dmc;
            const unsigned int* msp = mbase + (size_t)dmr*NN + (c+1)*KC + dmc;
            CPA16(dd, dsp); CPA16(dd+16u, dsp + 4);
            CPA16(md, msp); CPA16(md+16u, msp + 4);
            CP_COMMIT;
        }

        const int bb = c & 1;
        // ---- S = Q K^T (warp tile 16x16: 2 ct blocks of 8 keys) ----
        const float* sK = smf + K_F + bb*KSTR;
        float sacc[2][4] = {{0.f,0.f,0.f,0.f},{0.f,0.f,0.f,0.f}};
        #pragma unroll
        for (int kt = 0; kt < 8; kt++){
            const int k0 = 8*kt + fq;
            #pragma unroll
            for (int ct = 0; ct < 2; ct++){
                const float* kp = sK + (wc*16 + 8*ct + fr) * KP + k0;
                uint32_t b0 = f2tf32(kp[0]), b1 = f2tf32(kp[4]);
                mma_tf32(sacc[ct], qf[kt], b0, b1);
            }
        }

        // ---- fragment exp + P store + shuffle A-frags, per ct block ----
        const float* sD = smf + D_F + bb*DSTR;
        const uint32_t* sM = smu + M_F + bb*DSTR;
        const float* sV = smf + V_F + bb*VSTR;
        uint32_t a[2][4];

        #pragma unroll
        for (int ct = 0; ct < 2; ct++){
            const int ccl = wc*16 + 8*ct + 2*fq;     // chunk-local col
            float2 d0 = *(const float2*)(sD + r1*DMP + ccl);
            float2 d1 = *(const float2*)(sD + (r1+8)*DMP + ccl);
            uint2  m0 = *(const uint2*) (sM + r1*DMP + ccl);
            uint2  m1 = *(const uint2*) (sM + (r1+8)*DMP + ccl);
            float e0 = m0.x ? 0.f : __expf((sacc[ct][0] + d0.x) * 0.125f);
            float e1 = m0.y ? 0.f : __expf((sacc[ct][1] + d0.y) * 0.125f);
            float e2 = m1.x ? 0.f : __expf((sacc[ct][2] + d1.x) * 0.125f);
            float e3 = m1.y ? 0.f : __expf((sacc[ct][3] + d1.y) * 0.125f);
            psum0 += e0 + e1;
            psum1 += e2 + e3;
            uint32_t u0 = f2tf32(e0), u1 = f2tf32(e1), u2 = f2tf32(e2), u3 = f2tf32(e3);

            // store unnormalized P (32B-sector aligned per quad)
            float* pr = pbase + (size_t)r1 * NN + c*KC + ccl;
            *(uint2*)pr          = make_uint2(u0, u1);
            *(uint2*)(pr + 8*NN) = make_uint2(u2, u3);

            // C-layout -> A-layout via shuffles
            uint32_t s0a = __shfl_sync(0xffffffffu, u0, srcA);
            uint32_t s1a = __shfl_sync(0xffffffffu, u1, srcA);
            uint32_t s2a = __shfl_sync(0xffffffffu, u2, srcA);
            uint32_t s3a = __shfl_sync(0xffffffffu, u3, srcA);
            uint32_t s0b = __shfl_sync(0xffffffffu, u0, srcB);
            uint32_t s1b = __shfl_sync(0xffffffffu, u1, srcB);
            uint32_t s2b = __shfl_sync(0xffffffffu, u2, srcB);
            uint32_t s3b = __shfl_sync(0xffffffffu, u3, srcB);
            a[ct][0] = odd ? s1a : s0a;
            a[ct][1] = odd ? s3a : s2a;
            a[ct][2] = odd ? s1b : s0b;
            a[ct][3] = odd ? s3b : s2b;
        }

        // ---- PV: O_partial[16 x 64] += P(16x16) * V(16x64) ----
        #pragma unroll
        for (int dt = 0; dt < 8; dt++){
            #pragma unroll
            for (int ct = 0; ct < 2; ct++){
                const int vrow = wc*16 + 8*ct + fq;
                uint32_t b0 = f2tf32(sV[vrow       * VP + 8*dt + fr]);
                uint32_t b1 = f2tf32(sV[(vrow + 4) * VP + 8*dt + fr]);
                mma_tf32(oacc[dt], a[ct], b0, b1);
            }
        }
    }

    // ---- rowsum reduce ----
    {
        float v0 = psum0, v1 = psum1;
        v0 += __shfl_xor_sync(0xffffffffu, v0, 1);
        v0 += __shfl_xor_sync(0xffffffffu, v0, 2);
        v1 += __shfl_xor_sync(0xffffffffu, v1, 1);
        v1 += __shfl_xor_sync(0xffffffffu, v1, 2);
        if (fq == 0){
            atomicAdd(smf + RS_F + r1, v0);
            atomicAdd(smf + RS_F + r1 + 8, v1);
        }
    }
    // ---- O cross-warp (wc) reduce into scratch ----
    #pragma unroll
    for (int dt = 0; dt < 8; dt++){
        atomicAdd(smf + OS_F + r1*OP     + 8*dt + 2*fq,     oacc[dt][0]);
        atomicAdd(smf + OS_F + r1*OP     + 8*dt + 2*fq + 1, oacc[dt][1]);
        atomicAdd(smf + OS_F + (r1+8)*OP + 8*dt + 2*fq,     oacc[dt][2]);
        atomicAdd(smf + OS_F + (r1+8)*OP + 8*dt + 2*fq + 1, oacc[dt][3]);
    }
    __syncthreads();

    // ---- write O (scaled) ----
    {
        const float inv = 1.0f / smf[RS_F + dmr];
        const float* src = smf + OS_F + dmr*OP + dmc;
        float* dst = out + ((size_t)b * NN + row0 + dmr) * CC + h * DD + dmc;
        float4 a0 = *(const float4*)src;
        float4 a1 = *(const float4*)(src + 4);
        *(float4*)dst       = make_float4(a0.x*inv, a0.y*inv, a0.z*inv, a0.w*inv);
        *(float4*)(dst + 4) = make_float4(a1.x*inv, a1.y*inv, a1.z*inv, a1.w*inv);
    }

    // ---- renormalize own p_attn strip in place (L2-hot) ----
    {
        const float inv = 1.0f / smf[RS_F + dmr];
        float* prow = pbase + (size_t)dmr * NN;
        const int c0 = (tid & 7) * 4;
        #pragma unroll 4
        for (int j = 0; j < 32; j++){
            float* p4 = prow + c0 + 32*j;
            float4 pv = *(const float4*)p4;
            *(float4*)p4 = make_float4(pv.x*inv, pv.y*inv, pv.z*inv, pv.w*inv);
        }
    }
}

extern "C" void kernel_launch(void* const* d_in, const int* in_sizes, int n_in,
                              void* d_out, int out_size) {
    const float* q = (const float*)d_in[0];
    const float* k = (const float*)d_in[1];
    const float* v = (const float*)d_in[2];
    const unsigned int* mask = (const unsigned int*)d_in[3];
    const float* dis = (const float*)d_in[4];

    float* out  = (float*)d_out;
    float* pout = out + (size_t)BB * NN * CC;

    cudaFuncSetAttribute(attn_fuse64_kernel,
                         cudaFuncAttributeMaxDynamicSharedMemorySize, SMEM_BYTES);

    dim3 grid((NN / QT) * HEADS, BB, 1);
    attn_fuse64_kernel<<<grid, 256, SMEM_BYTES>>>(q, k, v, mask, dis, out, pout);
}

// round 17
// speedup vs baseline: 1.3446x; 1.3446x over previous
#include <cuda_runtime.h>
#include <math.h>
#include <stdint.h>

#define HEADS 4
#define BB 8
#define NN 1024
#define CC 256
#define DD 64
#define QT 32            // query rows per CTA
#define KC 32            // keys per chunk
#define NCH 32           // chunks

#define KP 68            // K pitch: (4fr+fq)%32 distinct -> conflict-free B frags
#define VP 72            // V pitch: (8fq+fr)%32 distinct -> conflict-free B frags
#define DP 36            // dis/mask chunk pitch
#define OP 68            // O scratch pitch

// float-index smem offsets
#define Q_F   0                     // 32*68          = 2176
#define K_F   2176                  // 2 * 32*68      = 4352
#define V_F   6528                  // 2 * 32*72      = 4608
#define D_F   11136                 // 2 * 32*36      = 2304
#define M_F   13440                 // 2 * 32*36      = 2304
#define OS_F  15744                 // 32*68          = 2176
#define RS_F  17920                 // 32
#define SMEM_FLOATS 17952
#define SMEM_BYTES (SMEM_FLOATS*4)  // 71808

#define KSTR (32*KP)
#define VSTR (32*VP)
#define DSTR (32*DP)

#define CP_COMMIT   asm volatile("cp.async.commit_group;" ::: "memory")
#define CP_WAIT0    asm volatile("cp.async.wait_group 0;" ::: "memory")

static __device__ __forceinline__ uint32_t s2u(const void* p){
    uint32_t a;
    asm("{ .reg .u64 t; cvta.to.shared.u64 t, %1; cvt.u32.u64 %0, t; }" : "=r"(a) : "l"(p));
    return a;
}
static __device__ __forceinline__ uint32_t f2tf32(float f){
    uint32_t u; asm("cvt.rna.tf32.f32 %0, %1;" : "=r"(u) : "f"(f)); return u;
}
static __device__ __forceinline__ void mma_tf32(float* c, const uint32_t* a,
                                                uint32_t b0, uint32_t b1){
    asm volatile("mma.sync.aligned.m16n8k8.row.col.f32.tf32.tf32.f32 "
        "{%0,%1,%2,%3}, {%4,%5,%6,%7}, {%8,%9}, {%0,%1,%2,%3};"
        : "+f"(c[0]), "+f"(c[1]), "+f"(c[2]), "+f"(c[3])
        : "r"(a[0]), "r"(a[1]), "r"(a[2]), "r"(a[3]), "r"(b0), "r"(b1));
}
#define CPA16(dst, src) \
    asm volatile("cp.async.ca.shared.global [%0], [%1], 16;" :: "r"(dst), "l"(src) : "memory")

__global__ __launch_bounds__(256, 2)
void attn_fuse_kernel(const float* __restrict__ q,
                      const float* __restrict__ k,
                      const float* __restrict__ v,
                      const unsigned int* __restrict__ mask,
                      const float* __restrict__ dis,
                      float* __restrict__ out,
                      float* __restrict__ pout)
{
    extern __shared__ float smf[];
    uint32_t* smu = (uint32_t*)smf;
    const uint32_t sbase = s2u(smf);

    const int tid  = threadIdx.x;
    const int wid  = tid >> 5;
    const int lane = tid & 31;
    const int fr = lane >> 2, fq = lane & 3;
    const int wr = wid >> 2, wc = wid & 3;     // 2 row-groups x 4 col-groups
    const int h    = blockIdx.x & 3;           // heads fastest -> dis/mask L2 reuse
    const int tile = blockIdx.x >> 2;
    const int b    = blockIdx.y;
    const int row0 = tile * QT;

    const float* qbase = q + ((size_t)b * NN + row0) * CC + h * DD;
    const float* kbase = k + ((size_t)b * NN) * CC + h * DD;
    const float* vbase = v + ((size_t)b * NN) * CC + h * DD;
    const float* disbase = dis + ((size_t)b * NN + row0) * NN;
    const unsigned int* mbase = mask + ((size_t)b * NN + row0) * NN;
    float* pbase = pout + (((size_t)h * BB + b) * NN + row0) * NN;

    // staging coords
    const int sr = tid >> 3;                   // 0..31
    const int sc = (tid & 7);                  // octet

    // ---- issue chunk 0 (K,V,dis,mask) ----
    {
        const float* ks = kbase + (size_t)sr * CC + sc*8;
        const float* vs = vbase + (size_t)sr * CC + sc*8;
        uint32_t kd = sbase + (K_F + sr*KP + sc*8)*4u;
        uint32_t vd = sbase + (V_F + sr*VP + sc*8)*4u;
        CPA16(kd, ks); CPA16(kd+16u, ks+4);
        CPA16(vd, vs); CPA16(vd+16u, vs+4);
        CPA16(sbase + (D_F + sr*DP + sc*4)*4u, disbase + (size_t)sr*NN + sc*4);
        CPA16(sbase + (M_F + sr*DP + sc*4)*4u, mbase   + (size_t)sr*NN + sc*4);
    }
    CP_COMMIT;

    // ---- stage Q (fp32 -> tf32), zero scratch ----
    {
        const float* src = qbase + (size_t)sr * CC + sc*8;
        float4 v0 = *(const float4*)src;
        float4 v1 = *(const float4*)(src + 4);
        uint32_t* d = smu + Q_F + sr * KP + sc*8;
        *(uint4*)d       = make_uint4(f2tf32(v0.x), f2tf32(v0.y), f2tf32(v0.z), f2tf32(v0.w));
        *(uint4*)(d + 4) = make_uint4(f2tf32(v1.x), f2tf32(v1.y), f2tf32(v1.z), f2tf32(v1.w));
    }
    for (int i = tid; i < 2176 + 32; i += 256) smf[OS_F + i] = 0.0f;
    __syncthreads();

    // ---- hoist Q fragments ----
    uint32_t qf[8][4];
    #pragma unroll
    for (int kt = 0; kt < 8; kt++){
        const uint32_t* q0 = smu + Q_F + (wr*16 + fr) * KP + 8*kt + fq;
        qf[kt][0] = q0[0];
        qf[kt][1] = q0[8*KP];
        qf[kt][2] = q0[4];
        qf[kt][3] = q0[8*KP + 4];
    }

    const int r1 = wr*16 + fr;         // CTA-local row
    const int ccl = wc*8 + 2*fq;       // chunk-local col
    const int srcA = (lane & 28) | (fq >> 1);
    const int srcB = srcA + 2;
    const bool odd = (fq & 1);

    float psum0 = 0.f, psum1 = 0.f;
    float oacc[8][4];
    #pragma unroll
    for (int dt = 0; dt < 8; dt++)
        #pragma unroll
        for (int i = 0; i < 4; i++) oacc[dt][i] = 0.f;

    // ================= fused mainloop =================
    for (int c = 0; c < NCH; c++){
        CP_WAIT0;
        __syncthreads();               // publish chunk c; retire reads of chunk c-1

        if (c + 1 < NCH){              // prefetch chunk c+1 into other buffers
            int bb1 = (c + 1) & 1;
            const float* ks = kbase + (size_t)((c+1)*KC + sr) * CC + sc*8;
            const float* vs = vbase + (size_t)((c+1)*KC + sr) * CC + sc*8;
            uint32_t kd = sbase + (K_F + bb1*KSTR + sr*KP + sc*8)*4u;
            uint32_t vd = sbase + (V_F + bb1*VSTR + sr*VP + sc*8)*4u;
            CPA16(kd, ks); CPA16(kd+16u, ks+4);
            CPA16(vd, vs); CPA16(vd+16u, vs+4);
            CPA16(sbase + (D_F + bb1*DSTR + sr*DP + sc*4)*4u,
                  disbase + (size_t)sr*NN + (c+1)*KC + sc*4);
            CPA16(sbase + (M_F + bb1*DSTR + sr*DP + sc*4)*4u,
                  mbase   + (size_t)sr*NN + (c+1)*KC + sc*4);
            CP_COMMIT;
        }

        const int bb = c & 1;
        // ---- dis/mask fragment loads hoisted: latency hides under the MMA chain ----
        const float* sD = smf + D_F + bb*DSTR;
        const uint32_t* sM = smu + M_F + bb*DSTR;
        float2 d0 = *(const float2*)(sD + r1*DP + ccl);
        float2 d1 = *(const float2*)(sD + (r1+8)*DP + ccl);
        uint2  m0 = *(const uint2*) (sM + r1*DP + ccl);
        uint2  m1 = *(const uint2*) (sM + (r1+8)*DP + ccl);

        // ---- S = Q K^T (warp tile 16x8) ----
        const float* sK = smf + K_F + bb*KSTR;
        float sacc[4] = {0.f, 0.f, 0.f, 0.f};
        #pragma unroll
        for (int kt = 0; kt < 8; kt++){
            const float* kp = sK + (wc*8 + fr) * KP + 8*kt + fq;
            uint32_t b0 = f2tf32(kp[0]), b1 = f2tf32(kp[4]);
            mma_tf32(sacc, qf[kt], b0, b1);
        }

        // ---- fragment exp ----
        float e0 = m0.x ? 0.f : __expf((sacc[0] + d0.x) * 0.125f);
        float e1 = m0.y ? 0.f : __expf((sacc[1] + d0.y) * 0.125f);
        float e2 = m1.x ? 0.f : __expf((sacc[2] + d1.x) * 0.125f);
        float e3 = m1.y ? 0.f : __expf((sacc[3] + d1.y) * 0.125f);
        psum0 += e0 + e1;
        psum1 += e2 + e3;
        uint32_t u0 = f2tf32(e0), u1 = f2tf32(e1), u2 = f2tf32(e2), u3 = f2tf32(e3);

        // ---- A-frags for PV via warp shuffles (C-layout -> A-layout) ----
        uint32_t a[4];
        {
            uint32_t s0a = __shfl_sync(0xffffffffu, u0, srcA);
            uint32_t s1a = __shfl_sync(0xffffffffu, u1, srcA);
            uint32_t s2a = __shfl_sync(0xffffffffu, u2, srcA);
            uint32_t s3a = __shfl_sync(0xffffffffu, u3, srcA);
            uint32_t s0b = __shfl_sync(0xffffffffu, u0, srcB);
            uint32_t s1b = __shfl_sync(0xffffffffu, u1, srcB);
            uint32_t s2b = __shfl_sync(0xffffffffu, u2, srcB);
            uint32_t s3b = __shfl_sync(0xffffffffu, u3, srcB);
            a[0] = odd ? s1a : s0a;    // (fr,   k=fq)
            a[1] = odd ? s3a : s2a;    // (fr+8, k=fq)
            a[2] = odd ? s1b : s0b;    // (fr,   k=fq+4)
            a[3] = odd ? s3b : s2b;    // (fr+8, k=fq+4)
        }

        // ---- PV: O_partial[16 x 64] += P(16x8) * V(8x64) ----
        const float* sV = smf + V_F + bb*VSTR;
        #pragma unroll
        for (int dt = 0; dt < 8; dt++){
            uint32_t b0 = f2tf32(sV[(wc*8 + fq)     * VP + 8*dt + fr]);
            uint32_t b1 = f2tf32(sV[(wc*8 + fq + 4) * VP + 8*dt + fr]);
            mma_tf32(oacc[dt], a, b0, b1);
        }

        // ---- store unnormalized P to gmem (after PV; fire-and-forget) ----
        {
            float* pr = pbase + (size_t)r1 * NN + c*KC + ccl;
            *(uint2*)pr           = make_uint2(u0, u1);
            *(uint2*)(pr + 8*NN)  = make_uint2(u2, u3);
        }
    }

    // ---- rowsum reduce ----
    {
        float v0 = psum0, v1 = psum1;
        v0 += __shfl_xor_sync(0xffffffffu, v0, 1);
        v0 += __shfl_xor_sync(0xffffffffu, v0, 2);
        v1 += __shfl_xor_sync(0xffffffffu, v1, 1);
        v1 += __shfl_xor_sync(0xffffffffu, v1, 2);
        if (fq == 0){
            atomicAdd(smf + RS_F + r1, v0);
            atomicAdd(smf + RS_F + r1 + 8, v1);
        }
    }
    // ---- O cross-warp (wc) reduce into scratch ----
    #pragma unroll
    for (int dt = 0; dt < 8; dt++){
        atomicAdd(smf + OS_F + r1*OP     + 8*dt + 2*fq,     oacc[dt][0]);
        atomicAdd(smf + OS_F + r1*OP     + 8*dt + 2*fq + 1, oacc[dt][1]);
        atomicAdd(smf + OS_F + (r1+8)*OP + 8*dt + 2*fq,     oacc[dt][2]);
        atomicAdd(smf + OS_F + (r1+8)*OP + 8*dt + 2*fq + 1, oacc[dt][3]);
    }
    __syncthreads();

    // ---- write O (scaled) ----
    {
        const float inv = 1.0f / smf[RS_F + sr];
        const float* src = smf + OS_F + sr*OP + sc*8;
        float* dst = out + ((size_t)b * NN + row0 + sr) * CC + h * DD + sc*8;
        float4 a0 = *(const float4*)src;
        float4 a1 = *(const float4*)(src + 4);
        *(float4*)dst       = make_float4(a0.x*inv, a0.y*inv, a0.z*inv, a0.w*inv);
        *(float4*)(dst + 4) = make_float4(a1.x*inv, a1.y*inv, a1.z*inv, a1.w*inv);
    }

    // ---- renormalize own p_attn strip in place (L2-hot) ----
    {
        const float inv = 1.0f / smf[RS_F + sr];
        float* prow = pbase + (size_t)sr * NN;
        #pragma unroll 4
        for (int j = 0; j < 32; j++){
            float* p4 = prow + sc*4 + 32*j;
            float4 pv = *(const float4*)p4;
            *(float4*)p4 = make_float4(pv.x*inv, pv.y*inv, pv.z*inv, pv.w*inv);
        }
    }
}

extern "C" void kernel_launch(void* const* d_in, const int* in_sizes, int n_in,
                              void* d_out, int out_size) {
    const float* q = (const float*)d_in[0];
    const float* k = (const float*)d_in[1];
    const float* v = (const float*)d_in[2];
    const unsigned int* mask = (const unsigned int*)d_in[3];
    const float* dis = (const float*)d_in[4];

    float* out  = (float*)d_out;
    float* pout = out + (size_t)BB * NN * CC;

    cudaFuncSetAttribute(attn_fuse_kernel,
                         cudaFuncAttributeMaxDynamicSharedMemorySize, SMEM_BYTES);

    dim3 grid((NN / QT) * HEADS, BB, 1);
    attn_fuse_kernel<<<grid, 256, SMEM_BYTES>>>(q, k, v, mask, dis, out, pout);
}